// round 2
// baseline (speedup 1.0000x reference)
#include <cuda_runtime.h>
#include <math.h>

// ---------------- problem constants ----------------
#define S_LEN 4096
#define HSIZE 1024
#define NHA   16
#define HD    64
#define NHL   4
#define DIN   256
#define CHUNK 1024
#define NC    4
#define NCH   16   // NC * NHL

// scratch offsets (in floats)
#define OFF_XN    0L
#define OFF_QKV   4194304L
#define OFF_ATTN  16777216L
#define OFF_C     20971520L
#define OFF_S0    25165824L
#define OFF_S1    29360128L
#define OFF_S2    33554432L
#define OFF_S3    37748736L
#define OFF_W0N   41943040L
#define OFF_W1N   42991616L
#define OFF_W2N   44040192L
#define SCRATCH_TOTAL 45088768L

#define CHD_STRIDE 262144L   // 1024*256 per chunk-head activation
#define W_STRIDE   65536L    // 256*256 per head weight

__device__ float g_scratch[SCRATCH_TOTAL];

// ---------------- LayerNorm ----------------
__global__ void ln_kernel(const float* __restrict__ x,
                          const float* __restrict__ w,
                          const float* __restrict__ b,
                          float* __restrict__ out) {
    int row = blockIdx.x;
    const float* xr = x + (long)row * HSIZE;
    float s = 0.f, ss = 0.f;
    for (int i = threadIdx.x; i < HSIZE; i += blockDim.x) {
        float v = xr[i]; s += v; ss += v * v;
    }
    __shared__ float red[64];
    for (int o = 16; o > 0; o >>= 1) {
        s  += __shfl_down_sync(0xffffffffu, s,  o);
        ss += __shfl_down_sync(0xffffffffu, ss, o);
    }
    int wid = threadIdx.x >> 5, lid = threadIdx.x & 31;
    if (lid == 0) { red[wid] = s; red[wid + 32] = ss; }
    __syncthreads();
    if (threadIdx.x == 0) {
        float ts = 0.f, tss = 0.f;
        int nw = blockDim.x >> 5;
        for (int i = 0; i < nw; i++) { ts += red[i]; tss += red[i + 32]; }
        float mean = ts / HSIZE;
        red[0] = mean;
        red[1] = tss / HSIZE - mean * mean;
    }
    __syncthreads();
    float mean = red[0];
    float inv = rsqrtf(red[1] + 1e-5f);
    float* orow = out + (long)row * HSIZE;
    for (int i = threadIdx.x; i < HSIZE; i += blockDim.x)
        orow[i] = (xr[i] - mean) * inv * w[i] + b[i];
}

// ---------------- generic batched SGEMM ----------------
// C[m,n] = sum_k A[m,k]*B[k,n] (+bias[n]) (+base[m,n])
// transA: A stored K-major (Astore[k*lda + m]); else Astore[m*lda + k]
// transB: B stored N-major (Bstore[n*ldb + k]); else Bstore[k*ldb + n]
struct GemmParams {
    const float* A; int lda; int transA; long strideA; int modA;
    const float* B; int ldb; int transB; long strideB; int modB;
    float* C; int ldc; long strideC; int modC;
    const float* bias;
    const float* base; int ldbase; long strideBase; int modBase;
    int M, N, K;
};

__global__ __launch_bounds__(256) void sgemm_kernel(GemmParams p) {
    __shared__ float As[16][68];
    __shared__ float Bs[16][68];
    const int z = blockIdx.z;
    const float* A = p.A + (long)(z % p.modA) * p.strideA;
    const float* B = p.B + (long)(z % p.modB) * p.strideB;
    float* C = p.C + (long)(z % p.modC) * p.strideC;
    const float* base = p.base ? p.base + (long)(z % p.modBase) * p.strideBase : nullptr;
    const int m0 = blockIdx.y * 64;
    const int n0 = blockIdx.x * 64;
    const int tid = threadIdx.x;
    const int tx = tid & 15, ty = tid >> 4;

    float acc[4][4] = {};
    for (int k0 = 0; k0 < p.K; k0 += 16) {
        if (!p.transA) {
            int m = tid >> 2, kq = (tid & 3) << 2;
            float4 v = *(const float4*)(A + (long)(m0 + m) * p.lda + k0 + kq);
            As[kq + 0][m] = v.x; As[kq + 1][m] = v.y;
            As[kq + 2][m] = v.z; As[kq + 3][m] = v.w;
        } else {
            int k = tid >> 4, m4 = (tid & 15) << 2;
            *(float4*)&As[k][m4] =
                *(const float4*)(A + (long)(k0 + k) * p.lda + m0 + m4);
        }
        if (p.transB) {
            int n = tid >> 2, kq = (tid & 3) << 2;
            float4 v = *(const float4*)(B + (long)(n0 + n) * p.ldb + k0 + kq);
            Bs[kq + 0][n] = v.x; Bs[kq + 1][n] = v.y;
            Bs[kq + 2][n] = v.z; Bs[kq + 3][n] = v.w;
        } else {
            int k = tid >> 4, n4 = (tid & 15) << 2;
            *(float4*)&Bs[k][n4] =
                *(const float4*)(B + (long)(k0 + k) * p.ldb + n0 + n4);
        }
        __syncthreads();
        #pragma unroll
        for (int k = 0; k < 16; k++) {
            float4 a4 = *(float4*)&As[k][ty << 2];
            float4 b4 = *(float4*)&Bs[k][tx << 2];
            float av[4] = {a4.x, a4.y, a4.z, a4.w};
            float bv[4] = {b4.x, b4.y, b4.z, b4.w};
            #pragma unroll
            for (int i = 0; i < 4; i++)
                #pragma unroll
                for (int j = 0; j < 4; j++)
                    acc[i][j] += av[i] * bv[j];
        }
        __syncthreads();
    }
    #pragma unroll
    for (int i = 0; i < 4; i++) {
        int m = m0 + (ty << 2) + i;
        #pragma unroll
        for (int j = 0; j < 4; j++) {
            int n = n0 + (tx << 2) + j;
            float v = acc[i][j];
            if (p.bias) v += p.bias[n];
            if (base)   v += base[(long)m * p.ldbase + n];
            C[(long)m * p.ldc + n] = v;
        }
    }
}

// ---------------- flash attention ----------------
// grid: (64 q-tiles, 16 heads), 256 threads, dynamic smem.
// qkv layout: row s, cols [0,1024)=q [1024,2048)=k [2048,3072)=v
#define ATT_SMEM_FLOATS (4 * 64 * 68 + 192)
__global__ __launch_bounds__(256) void attn_kernel(const float* __restrict__ qkv,
                                                   float* __restrict__ out) {
    extern __shared__ float sm[];
    float* Qt = sm;                 // [d][r], pitch 68
    float* Kt = sm + 64 * 68;       // [d][c]
    float* Vs = sm + 2 * 64 * 68;   // [k][c]
    float* St = sm + 3 * 64 * 68;   // [j][r]
    float* m_sh  = sm + 4 * 64 * 68;
    float* l_sh  = m_sh + 64;
    float* al_sh = l_sh + 64;

    const int h = blockIdx.y, qt = blockIdx.x;
    const int tid = threadIdx.x, tx = tid & 15, ty = tid >> 4;

    for (int idx = tid; idx < 64 * 64; idx += 256) {
        int r = idx >> 6, d = idx & 63;
        Qt[d * 68 + r] = qkv[(long)(qt * 64 + r) * 3072 + h * 64 + d] * 0.125f;
    }
    if (tid < 64) { m_sh[tid] = -1e30f; l_sh[tid] = 0.f; }
    float acc[4][4] = {};
    __syncthreads();

    for (int kt = 0; kt < 64; kt++) {
        for (int idx = tid; idx < 64 * 64; idx += 256) {
            int r = idx >> 6, d = idx & 63;
            long base = (long)(kt * 64 + r) * 3072 + h * 64 + d;
            Kt[d * 68 + r] = qkv[base + 1024];
            Vs[r * 68 + d] = qkv[base + 2048];
        }
        __syncthreads();

        float s[4][4] = {};
        #pragma unroll 4
        for (int d = 0; d < 64; d++) {
            float4 a4 = *(float4*)&Qt[d * 68 + (ty << 2)];
            float4 b4 = *(float4*)&Kt[d * 68 + (tx << 2)];
            float av[4] = {a4.x, a4.y, a4.z, a4.w};
            float bv[4] = {b4.x, b4.y, b4.z, b4.w};
            #pragma unroll
            for (int i = 0; i < 4; i++)
                #pragma unroll
                for (int j = 0; j < 4; j++)
                    s[i][j] += av[i] * bv[j];
        }
        #pragma unroll
        for (int j = 0; j < 4; j++) {
            float4 v = make_float4(s[0][j], s[1][j], s[2][j], s[3][j]);
            *(float4*)&St[((tx << 2) + j) * 68 + (ty << 2)] = v;
        }
        __syncthreads();

        if (tid < 64) {
            int r = tid;
            float mold = m_sh[r], mnew = mold;
            for (int j = 0; j < 64; j++) mnew = fmaxf(mnew, St[j * 68 + r]);
            float sum = 0.f;
            for (int j = 0; j < 64; j++) {
                float pv = __expf(St[j * 68 + r] - mnew);
                St[j * 68 + r] = pv;
                sum += pv;
            }
            float al = __expf(mold - mnew);
            l_sh[r] = l_sh[r] * al + sum;
            m_sh[r] = mnew;
            al_sh[r] = al;
        }
        __syncthreads();

        float alr[4];
        #pragma unroll
        for (int i = 0; i < 4; i++) alr[i] = al_sh[(ty << 2) + i];
        #pragma unroll
        for (int i = 0; i < 4; i++)
            #pragma unroll
            for (int j = 0; j < 4; j++) acc[i][j] *= alr[i];

        #pragma unroll 4
        for (int k = 0; k < 64; k++) {
            float4 p4 = *(float4*)&St[k * 68 + (ty << 2)];
            float4 v4 = *(float4*)&Vs[k * 68 + (tx << 2)];
            float pv[4] = {p4.x, p4.y, p4.z, p4.w};
            float vv[4] = {v4.x, v4.y, v4.z, v4.w};
            #pragma unroll
            for (int i = 0; i < 4; i++)
                #pragma unroll
                for (int j = 0; j < 4; j++)
                    acc[i][j] += pv[i] * vv[j];
        }
        __syncthreads();
    }

    float linv[4];
    #pragma unroll
    for (int i = 0; i < 4; i++) linv[i] = 1.f / l_sh[(ty << 2) + i];
    #pragma unroll
    for (int i = 0; i < 4; i++) {
        long row = (long)(qt * 64 + (ty << 2) + i) * HSIZE + h * 64;
        #pragma unroll
        for (int j = 0; j < 4; j++)
            out[row + (tx << 2) + j] = acc[i][j] * linv[i];
    }
}

// ---------------- LaCT helpers ----------------
// xn[s, h*256+d] -> c[ch, cc, d]   (ch = n*4+h)
__global__ void reshape_kernel(const float* __restrict__ xn, float* __restrict__ c) {
    int idx = blockIdx.x * 256 + threadIdx.x;
    int d  = idx & 255;
    int cc = (idx >> 8) & 1023;
    int ch = idx >> 18;
    int n = ch >> 2, h = ch & 3;
    c[idx] = xn[(long)(n * CHUNK + cc) * HSIZE + h * DIN + d];
}

// out[s, h*256+d] += oq[ch, cc, d]
__global__ void scatter_kernel(const float* __restrict__ oq, float* __restrict__ out) {
    int idx = blockIdx.x * 256 + threadIdx.x;
    int d  = idx & 255;
    int cc = (idx >> 8) & 1023;
    int ch = idx >> 18;
    int n = ch >> 2, h = ch & 3;
    long o = (long)(n * CHUNK + cc) * HSIZE + h * DIN + d;
    out[o] += oq[idx];
}

// inputs: s0=gate, s1=g, s2=u (= kv@w1)
// outputs: s3=hidden, s0=P=u*g*silu'(gate), s1=Q2=u*h
__global__ void ew1_kernel(float* __restrict__ s0, float* __restrict__ s1,
                           const float* __restrict__ s2, float* __restrict__ s3) {
    int i = blockIdx.x * 256 + threadIdx.x;
    float gate = s0[i], g = s1[i], u = s2[i];
    float sg = 1.f / (1.f + __expf(-gate));
    float hh = gate * sg;
    s3[i] = hh * g;
    s0[i] = u * g * sg * (1.f + gate * (1.f - sg));
    s1[i] = u * hh;
}

// s2 = silu(s0) * s1
__global__ void ew2_kernel(const float* __restrict__ s0, const float* __restrict__ s1,
                           float* __restrict__ s2) {
    int i = blockIdx.x * 256 + threadIdx.x;
    float gq = s0[i], gq2 = s1[i];
    float sg = 1.f / (1.f + __expf(-gq));
    s2[i] = gq * sg * gq2;
}

// ---------------- host launcher ----------------
static void run_gemm(int M, int N, int K,
                     const float* A, int lda, int tA, long sA, int mA,
                     const float* B, int ldb, int tB, long sB, int mB,
                     float* C, int ldc, long sC, int mC,
                     const float* bias,
                     const float* base, int ldbase, long sBase, int mBase,
                     int batch) {
    GemmParams p;
    p.A = A; p.lda = lda; p.transA = tA; p.strideA = sA; p.modA = mA > 0 ? mA : 1;
    p.B = B; p.ldb = ldb; p.transB = tB; p.strideB = sB; p.modB = mB > 0 ? mB : 1;
    p.C = C; p.ldc = ldc; p.strideC = sC; p.modC = mC > 0 ? mC : 1;
    p.bias = bias;
    p.base = base; p.ldbase = ldbase; p.strideBase = sBase; p.modBase = mBase > 0 ? mBase : 1;
    p.M = M; p.N = N; p.K = K;
    dim3 grid(N / 64, M / 64, batch);
    sgemm_kernel<<<grid, 256>>>(p);
}

extern "C" void kernel_launch(void* const* d_in, const int* in_sizes, int n_in,
                              void* d_out, int out_size) {
    const float* x     = (const float*)d_in[0];
    const float* ln_w  = (const float*)d_in[1];
    const float* ln_b  = (const float*)d_in[2];
    const float* in_w  = (const float*)d_in[3];
    const float* in_b  = (const float*)d_in[4];
    const float* ou_w  = (const float*)d_in[5];
    const float* ou_b  = (const float*)d_in[6];
    const float* w0    = (const float*)d_in[7];
    const float* w1    = (const float*)d_in[8];
    const float* w2    = (const float*)d_in[9];
    float* out = (float*)d_out;

    float* scr = nullptr;
    cudaGetSymbolAddress((void**)&scr, g_scratch);
    float* xn   = scr + OFF_XN;
    float* qkvb = scr + OFF_QKV;
    float* attn = scr + OFF_ATTN;
    float* cbuf = scr + OFF_C;
    float* s0   = scr + OFF_S0;
    float* s1   = scr + OFF_S1;
    float* s2   = scr + OFF_S2;
    float* s3   = scr + OFF_S3;
    float* w0n  = scr + OFF_W0N;
    float* w1n  = scr + OFF_W1N;
    float* w2n  = scr + OFF_W2N;

    // 1. LayerNorm
    ln_kernel<<<S_LEN, 256>>>(x, ln_w, ln_b, xn);

    // 2. qkv = xn @ in_proj_w^T + b   [4096,3072]
    run_gemm(4096, 3072, 1024,
             xn, 1024, 0, 0, 1,
             in_w, 1024, 1, 0, 1,
             qkvb, 3072, 0, 1,
             in_b, nullptr, 0, 0, 1, 1);

    // 3. contiguous kv per chunk-head
    reshape_kernel<<<16384, 256>>>(xn, cbuf);

    // 4. flash attention
    cudaFuncSetAttribute(attn_kernel, cudaFuncAttributeMaxDynamicSharedMemorySize,
                         ATT_SMEM_FLOATS * 4);
    attn_kernel<<<dim3(64, 16), 256, ATT_SMEM_FLOATS * 4>>>(qkvb, attn);

    // 5. attn_out = attn @ out_proj_w^T + b  -> d_out
    run_gemm(4096, 1024, 1024,
             attn, 1024, 0, 0, 1,
             ou_w, 1024, 1, 0, 1,
             out, 1024, 0, 1,
             ou_b, nullptr, 0, 0, 1, 1);

    // 6. gate = kv @ w0^T ; g = kv @ w2^T ; u = kv @ w1  (batched over 16 chunk-heads)
    run_gemm(1024, 256, 256,
             cbuf, 256, 0, CHD_STRIDE, 16,
             w0, 256, 1, W_STRIDE, 4,
             s0, 256, CHD_STRIDE, 16,
             nullptr, nullptr, 0, 0, 1, 16);
    run_gemm(1024, 256, 256,
             cbuf, 256, 0, CHD_STRIDE, 16,
             w2, 256, 1, W_STRIDE, 4,
             s1, 256, CHD_STRIDE, 16,
             nullptr, nullptr, 0, 0, 1, 16);
    run_gemm(1024, 256, 256,
             cbuf, 256, 0, CHD_STRIDE, 16,
             w1, 256, 0, W_STRIDE, 4,
             s2, 256, CHD_STRIDE, 16,
             nullptr, nullptr, 0, 0, 1, 16);

    // 7. elementwise: hidden, P, Q2
    ew1_kernel<<<16384, 256>>>(s0, s1, s2, s3);

    // 8. w1n = w1 + kv^T @ hidden ; w0n = w0 + P^T @ kv ; w2n = w2 + Q2^T @ kv
    run_gemm(256, 256, 1024,
             cbuf, 256, 1, CHD_STRIDE, 16,
             s3, 256, 0, CHD_STRIDE, 16,
             w1n, 256, W_STRIDE, 16,
             nullptr, w1, 256, W_STRIDE, 4, 16);
    run_gemm(256, 256, 1024,
             s0, 256, 1, CHD_STRIDE, 16,
             cbuf, 256, 0, CHD_STRIDE, 16,
             w0n, 256, W_STRIDE, 16,
             nullptr, w0, 256, W_STRIDE, 4, 16);
    run_gemm(256, 256, 1024,
             s1, 256, 1, CHD_STRIDE, 16,
             cbuf, 256, 0, CHD_STRIDE, 16,
             w2n, 256, W_STRIDE, 16,
             nullptr, w2, 256, W_STRIDE, 4, 16);

    // 9. gq = kv @ w0n^T ; gq2 = kv @ w2n^T
    run_gemm(1024, 256, 256,
             cbuf, 256, 0, CHD_STRIDE, 16,
             w0n, 256, 1, W_STRIDE, 16,
             s0, 256, CHD_STRIDE, 16,
             nullptr, nullptr, 0, 0, 1, 16);
    run_gemm(1024, 256, 256,
             cbuf, 256, 0, CHD_STRIDE, 16,
             w2n, 256, 1, W_STRIDE, 16,
             s1, 256, CHD_STRIDE, 16,
             nullptr, nullptr, 0, 0, 1, 16);

    // 10. X = silu(gq) * gq2
    ew2_kernel<<<16384, 256>>>(s0, s1, s2);

    // 11. oq = X @ w1n^T
    run_gemm(1024, 256, 256,
             s2, 256, 0, CHD_STRIDE, 16,
             w1n, 256, 1, W_STRIDE, 16,
             s3, 256, CHD_STRIDE, 16,
             nullptr, nullptr, 0, 0, 1, 16);

    // 12. d_out += scattered oq
    scatter_kernel<<<16384, 256>>>(s3, out);
}

// round 3
// speedup vs baseline: 2.1009x; 2.1009x over previous
#include <cuda_runtime.h>
#include <math.h>

// ---------------- problem constants ----------------
#define S_LEN 4096
#define HSIZE 1024
#define NHA   16
#define HD    64
#define NHL   4
#define DIN   256
#define CHUNK 1024
#define NC    4
#define NCH   16   // NC * NHL

// scratch offsets (in floats)
#define OFF_XN    0L
#define OFF_QKV   4194304L
#define OFF_ATTN  16777216L
#define OFF_C     20971520L
#define OFF_S0    25165824L
#define OFF_S1    29360128L
#define OFF_S2    33554432L
#define OFF_S3    37748736L
#define OFF_W0N   41943040L
#define OFF_W1N   42991616L
#define OFF_W2N   44040192L
#define SCRATCH_TOTAL 45088768L

#define CHD_STRIDE 262144L   // 1024*256 per chunk-head activation
#define W_STRIDE   65536L    // 256*256 per head weight

__device__ float g_scratch[SCRATCH_TOTAL];

// ---------------- tf32 helpers ----------------
__device__ __forceinline__ float tf32r(float x) {
    unsigned r;
    asm("cvt.rna.tf32.f32 %0, %1;" : "=r"(r) : "f"(x));
    return __uint_as_float(r);
}

__device__ __forceinline__ void mma_tf32(float* c, const unsigned* a, const unsigned* b) {
    asm volatile(
        "mma.sync.aligned.m16n8k8.row.col.f32.tf32.tf32.f32 "
        "{%0,%1,%2,%3}, {%4,%5,%6,%7}, {%8,%9}, {%0,%1,%2,%3};"
        : "+f"(c[0]), "+f"(c[1]), "+f"(c[2]), "+f"(c[3])
        : "r"(a[0]), "r"(a[1]), "r"(a[2]), "r"(a[3]), "r"(b[0]), "r"(b[1]));
}

// ---------------- LayerNorm ----------------
__global__ void ln_kernel(const float* __restrict__ x,
                          const float* __restrict__ w,
                          const float* __restrict__ b,
                          float* __restrict__ out) {
    int row = blockIdx.x;
    const float* xr = x + (long)row * HSIZE;
    float s = 0.f, ss = 0.f;
    for (int i = threadIdx.x; i < HSIZE; i += blockDim.x) {
        float v = xr[i]; s += v; ss += v * v;
    }
    __shared__ float red[64];
    for (int o = 16; o > 0; o >>= 1) {
        s  += __shfl_down_sync(0xffffffffu, s,  o);
        ss += __shfl_down_sync(0xffffffffu, ss, o);
    }
    int wid = threadIdx.x >> 5, lid = threadIdx.x & 31;
    if (lid == 0) { red[wid] = s; red[wid + 32] = ss; }
    __syncthreads();
    if (threadIdx.x == 0) {
        float ts = 0.f, tss = 0.f;
        int nw = blockDim.x >> 5;
        for (int i = 0; i < nw; i++) { ts += red[i]; tss += red[i + 32]; }
        float mean = ts / HSIZE;
        red[0] = mean;
        red[1] = tss / HSIZE - mean * mean;
    }
    __syncthreads();
    float mean = red[0];
    float inv = rsqrtf(red[1] + 1e-5f);
    float* orow = out + (long)row * HSIZE;
    for (int i = threadIdx.x; i < HSIZE; i += blockDim.x)
        orow[i] = (xr[i] - mean) * inv * w[i] + b[i];
}

// ---------------- generic batched TF32 tensor-core GEMM ----------------
// C[m,n] = sum_k A[m,k]*B[k,n] (+bias[n]) (+base[m,n])
// transA: A stored K-major (Astore[k*lda + m]); else Astore[m*lda + k]
// transB: B stored N-major (Bstore[n*ldb + k]); else Bstore[k*ldb + n]
// Block tile 128x128x16, 8 warps each 64x32, m16n8k8 tf32 mma,
// double-buffered smem with register prefetch.
struct GemmParams {
    const float* A; int lda; int transA; long strideA; int modA;
    const float* B; int ldb; int transB; long strideB; int modB;
    float* C; int ldc; long strideC; int modC;
    const float* bias;
    const float* base; int ldbase; long strideBase; int modBase;
    int M, N, K;
};

#define GP 136   // smem pitch (floats): 136 % 32 == 8 -> conflict-free frag loads

__global__ __launch_bounds__(256) void tgemm_kernel(GemmParams p) {
    __shared__ float As[2][16 * GP];
    __shared__ float Bs[2][16 * GP];

    const int z = blockIdx.z;
    const float* A = p.A + (long)(z % p.modA) * p.strideA;
    const float* B = p.B + (long)(z % p.modB) * p.strideB;
    float* C = p.C + (long)(z % p.modC) * p.strideC;
    const float* base = p.base ? p.base + (long)(z % p.modBase) * p.strideBase : nullptr;

    const int m0 = blockIdx.y * 128;
    const int n0 = blockIdx.x * 128;
    const int tid = threadIdx.x;
    const int lane = tid & 31, w = tid >> 5;
    const int wm = (w >> 2) * 64;     // warp row offset (0 or 64)
    const int wn = (w & 3) * 32;      // warp col offset (0..96)
    const int fr = lane >> 2, fc = lane & 3;

    float acc[4][4][4];
    #pragma unroll
    for (int i = 0; i < 4; i++)
        #pragma unroll
        for (int j = 0; j < 4; j++)
            #pragma unroll
            for (int q = 0; q < 4; q++) acc[i][j][q] = 0.f;

    float4 ra0, ra1, rb0, rb1;

    auto loadA = [&](int k0) {
        if (!p.transA) {
            int m = tid >> 1, kq = (tid & 1) * 8;
            const float* src = A + (long)(m0 + m) * p.lda + k0 + kq;
            ra0 = *(const float4*)src;
            ra1 = *(const float4*)(src + 4);
        } else {
            int k1 = tid >> 5, m4 = (tid & 31) * 4;
            ra0 = *(const float4*)(A + (long)(k0 + k1) * p.lda + m0 + m4);
            int id = tid + 256;
            int k2 = id >> 5, m42 = (id & 31) * 4;
            ra1 = *(const float4*)(A + (long)(k0 + k2) * p.lda + m0 + m42);
        }
    };
    auto storeA = [&](int buf) {
        float* s = As[buf];
        if (!p.transA) {
            int m = tid >> 1, kq = (tid & 1) * 8;
            s[(kq + 0) * GP + m] = tf32r(ra0.x);
            s[(kq + 1) * GP + m] = tf32r(ra0.y);
            s[(kq + 2) * GP + m] = tf32r(ra0.z);
            s[(kq + 3) * GP + m] = tf32r(ra0.w);
            s[(kq + 4) * GP + m] = tf32r(ra1.x);
            s[(kq + 5) * GP + m] = tf32r(ra1.y);
            s[(kq + 6) * GP + m] = tf32r(ra1.z);
            s[(kq + 7) * GP + m] = tf32r(ra1.w);
        } else {
            int k1 = tid >> 5, m4 = (tid & 31) * 4;
            s[k1 * GP + m4 + 0] = tf32r(ra0.x);
            s[k1 * GP + m4 + 1] = tf32r(ra0.y);
            s[k1 * GP + m4 + 2] = tf32r(ra0.z);
            s[k1 * GP + m4 + 3] = tf32r(ra0.w);
            int id = tid + 256;
            int k2 = id >> 5, m42 = (id & 31) * 4;
            s[k2 * GP + m42 + 0] = tf32r(ra1.x);
            s[k2 * GP + m42 + 1] = tf32r(ra1.y);
            s[k2 * GP + m42 + 2] = tf32r(ra1.z);
            s[k2 * GP + m42 + 3] = tf32r(ra1.w);
        }
    };
    auto loadB = [&](int k0) {
        if (p.transB) {
            int n = tid >> 1, kq = (tid & 1) * 8;
            const float* src = B + (long)(n0 + n) * p.ldb + k0 + kq;
            rb0 = *(const float4*)src;
            rb1 = *(const float4*)(src + 4);
        } else {
            int k1 = tid >> 5, n4 = (tid & 31) * 4;
            rb0 = *(const float4*)(B + (long)(k0 + k1) * p.ldb + n0 + n4);
            int id = tid + 256;
            int k2 = id >> 5, n42 = (id & 31) * 4;
            rb1 = *(const float4*)(B + (long)(k0 + k2) * p.ldb + n0 + n42);
        }
    };
    auto storeB = [&](int buf) {
        float* s = Bs[buf];
        if (p.transB) {
            int n = tid >> 1, kq = (tid & 1) * 8;
            s[(kq + 0) * GP + n] = tf32r(rb0.x);
            s[(kq + 1) * GP + n] = tf32r(rb0.y);
            s[(kq + 2) * GP + n] = tf32r(rb0.z);
            s[(kq + 3) * GP + n] = tf32r(rb0.w);
            s[(kq + 4) * GP + n] = tf32r(rb1.x);
            s[(kq + 5) * GP + n] = tf32r(rb1.y);
            s[(kq + 6) * GP + n] = tf32r(rb1.z);
            s[(kq + 7) * GP + n] = tf32r(rb1.w);
        } else {
            int k1 = tid >> 5, n4 = (tid & 31) * 4;
            s[k1 * GP + n4 + 0] = tf32r(rb0.x);
            s[k1 * GP + n4 + 1] = tf32r(rb0.y);
            s[k1 * GP + n4 + 2] = tf32r(rb0.z);
            s[k1 * GP + n4 + 3] = tf32r(rb0.w);
            int id = tid + 256;
            int k2 = id >> 5, n42 = (id & 31) * 4;
            s[k2 * GP + n42 + 0] = tf32r(rb1.x);
            s[k2 * GP + n42 + 1] = tf32r(rb1.y);
            s[k2 * GP + n42 + 2] = tf32r(rb1.z);
            s[k2 * GP + n42 + 3] = tf32r(rb1.w);
        }
    };

    const int nt = p.K >> 4;
    loadA(0); loadB(0);
    storeA(0); storeB(0);
    __syncthreads();

    for (int t = 0; t < nt; t++) {
        const int cur = t & 1;
        if (t + 1 < nt) { loadA((t + 1) << 4); loadB((t + 1) << 4); }

        #pragma unroll
        for (int ks = 0; ks < 2; ks++) {
            const int k0 = ks * 8;
            unsigned af[4][4], bf[4][2];
            #pragma unroll
            for (int mt = 0; mt < 4; mt++) {
                int m = wm + mt * 16 + fr;
                af[mt][0] = __float_as_uint(As[cur][(k0 + fc) * GP + m]);
                af[mt][1] = __float_as_uint(As[cur][(k0 + fc) * GP + m + 8]);
                af[mt][2] = __float_as_uint(As[cur][(k0 + fc + 4) * GP + m]);
                af[mt][3] = __float_as_uint(As[cur][(k0 + fc + 4) * GP + m + 8]);
            }
            #pragma unroll
            for (int ntl = 0; ntl < 4; ntl++) {
                int n = wn + ntl * 8 + fr;
                bf[ntl][0] = __float_as_uint(Bs[cur][(k0 + fc) * GP + n]);
                bf[ntl][1] = __float_as_uint(Bs[cur][(k0 + fc + 4) * GP + n]);
            }
            #pragma unroll
            for (int mt = 0; mt < 4; mt++)
                #pragma unroll
                for (int ntl = 0; ntl < 4; ntl++)
                    mma_tf32(acc[mt][ntl], af[mt], bf[ntl]);
        }

        if (t + 1 < nt) { storeA(cur ^ 1); storeB(cur ^ 1); }
        __syncthreads();
    }

    // epilogue
    #pragma unroll
    for (int mt = 0; mt < 4; mt++) {
        int row0 = m0 + wm + mt * 16 + fr;
        #pragma unroll
        for (int ntl = 0; ntl < 4; ntl++) {
            int col = n0 + wn + ntl * 8 + 2 * fc;
            float v0 = acc[mt][ntl][0], v1 = acc[mt][ntl][1];
            float v2 = acc[mt][ntl][2], v3 = acc[mt][ntl][3];
            if (p.bias) {
                float b0 = p.bias[col], b1 = p.bias[col + 1];
                v0 += b0; v1 += b1; v2 += b0; v3 += b1;
            }
            if (base) {
                v0 += base[(long)row0 * p.ldbase + col];
                v1 += base[(long)row0 * p.ldbase + col + 1];
                v2 += base[(long)(row0 + 8) * p.ldbase + col];
                v3 += base[(long)(row0 + 8) * p.ldbase + col + 1];
            }
            *(float2*)&C[(long)row0 * p.ldc + col] = make_float2(v0, v1);
            *(float2*)&C[(long)(row0 + 8) * p.ldc + col] = make_float2(v2, v3);
        }
    }
}

// ---------------- tensor-core flash attention ----------------
// grid (64 q-tiles, 16 heads), 128 threads (4 warps). Each warp owns 16 q rows.
// qkv layout: row s, cols [0,1024)=q [1024,2048)=k [2048,3072)=v
#define AP 68
#define ATT_SMEM_FLOATS (4 * 64 * AP)
__global__ __launch_bounds__(128) void attn_tc_kernel(const float* __restrict__ qkv,
                                                      float* __restrict__ out) {
    extern __shared__ float sm[];
    float* Qs = sm;                 // [m][d]   pitch AP (tf32)
    float* Kt = sm + 64 * AP;       // [d][key] pitch AP (tf32)
    float* Vs = sm + 2 * 64 * AP;   // [key][d] pitch AP (tf32)
    float* St = sm + 3 * 64 * AP;   // [row][key] P (tf32)

    const int h = blockIdx.y, qt = blockIdx.x;
    const int tid = threadIdx.x, lane = tid & 31, w = tid >> 5;
    const int fr = lane >> 2, fc = lane & 3;
    const int mrow = w * 16;

    // load Q tile (scaled, tf32)
    for (int i = tid; i < 64 * 16; i += 128) {
        int row = i >> 4, dq = (i & 15) * 4;
        float4 v = *(const float4*)(qkv + (long)(qt * 64 + row) * 3072 + h * 64 + dq);
        Qs[row * AP + dq + 0] = tf32r(v.x * 0.125f);
        Qs[row * AP + dq + 1] = tf32r(v.y * 0.125f);
        Qs[row * AP + dq + 2] = tf32r(v.z * 0.125f);
        Qs[row * AP + dq + 3] = tf32r(v.w * 0.125f);
    }

    float o[8][4];
    #pragma unroll
    for (int i = 0; i < 8; i++)
        #pragma unroll
        for (int j = 0; j < 4; j++) o[i][j] = 0.f;
    float m0 = -1e30f, m1 = -1e30f, l0 = 0.f, l1 = 0.f;
    __syncthreads();

    for (int kt = 0; kt < 64; kt++) {
        // load K (transposed) and V tiles
        for (int i = tid; i < 64 * 16; i += 128) {
            int row = i >> 4, dq = (i & 15) * 4;
            long bidx = (long)(kt * 64 + row) * 3072 + h * 64 + dq;
            float4 kv4 = *(const float4*)(qkv + bidx + 1024);
            Kt[(dq + 0) * AP + row] = tf32r(kv4.x);
            Kt[(dq + 1) * AP + row] = tf32r(kv4.y);
            Kt[(dq + 2) * AP + row] = tf32r(kv4.z);
            Kt[(dq + 3) * AP + row] = tf32r(kv4.w);
            float4 vv4 = *(const float4*)(qkv + bidx + 2048);
            Vs[row * AP + dq + 0] = tf32r(vv4.x);
            Vs[row * AP + dq + 1] = tf32r(vv4.y);
            Vs[row * AP + dq + 2] = tf32r(vv4.z);
            Vs[row * AP + dq + 3] = tf32r(vv4.w);
        }
        __syncthreads();

        // S = Q K^T  (16x64 per warp)
        float s[8][4];
        #pragma unroll
        for (int i = 0; i < 8; i++)
            #pragma unroll
            for (int j = 0; j < 4; j++) s[i][j] = 0.f;
        #pragma unroll
        for (int ks = 0; ks < 8; ks++) {
            const int k0 = ks * 8;
            unsigned af[4];
            af[0] = __float_as_uint(Qs[(mrow + fr) * AP + k0 + fc]);
            af[1] = __float_as_uint(Qs[(mrow + fr + 8) * AP + k0 + fc]);
            af[2] = __float_as_uint(Qs[(mrow + fr) * AP + k0 + fc + 4]);
            af[3] = __float_as_uint(Qs[(mrow + fr + 8) * AP + k0 + fc + 4]);
            #pragma unroll
            for (int ntl = 0; ntl < 8; ntl++) {
                unsigned bf[2];
                bf[0] = __float_as_uint(Kt[(k0 + fc) * AP + ntl * 8 + fr]);
                bf[1] = __float_as_uint(Kt[(k0 + fc + 4) * AP + ntl * 8 + fr]);
                mma_tf32(s[ntl], af, bf);
            }
        }

        // online softmax (rows mrow+fr and mrow+fr+8)
        float mx0 = m0, mx1 = m1;
        #pragma unroll
        for (int ntl = 0; ntl < 8; ntl++) {
            mx0 = fmaxf(mx0, fmaxf(s[ntl][0], s[ntl][1]));
            mx1 = fmaxf(mx1, fmaxf(s[ntl][2], s[ntl][3]));
        }
        mx0 = fmaxf(mx0, __shfl_xor_sync(0xffffffffu, mx0, 1));
        mx0 = fmaxf(mx0, __shfl_xor_sync(0xffffffffu, mx0, 2));
        mx1 = fmaxf(mx1, __shfl_xor_sync(0xffffffffu, mx1, 1));
        mx1 = fmaxf(mx1, __shfl_xor_sync(0xffffffffu, mx1, 2));

        float sum0 = 0.f, sum1 = 0.f;
        #pragma unroll
        for (int ntl = 0; ntl < 8; ntl++) {
            int col = ntl * 8 + 2 * fc;
            float p0 = __expf(s[ntl][0] - mx0);
            float p1 = __expf(s[ntl][1] - mx0);
            float p2 = __expf(s[ntl][2] - mx1);
            float p3 = __expf(s[ntl][3] - mx1);
            sum0 += p0 + p1;
            sum1 += p2 + p3;
            *(float2*)&St[(mrow + fr) * AP + col] = make_float2(tf32r(p0), tf32r(p1));
            *(float2*)&St[(mrow + fr + 8) * AP + col] = make_float2(tf32r(p2), tf32r(p3));
        }
        sum0 += __shfl_xor_sync(0xffffffffu, sum0, 1);
        sum0 += __shfl_xor_sync(0xffffffffu, sum0, 2);
        sum1 += __shfl_xor_sync(0xffffffffu, sum1, 1);
        sum1 += __shfl_xor_sync(0xffffffffu, sum1, 2);

        float al0 = __expf(m0 - mx0);
        float al1 = __expf(m1 - mx1);
        l0 = l0 * al0 + sum0;
        l1 = l1 * al1 + sum1;
        m0 = mx0; m1 = mx1;
        #pragma unroll
        for (int ntl = 0; ntl < 8; ntl++) {
            o[ntl][0] *= al0; o[ntl][1] *= al0;
            o[ntl][2] *= al1; o[ntl][3] *= al1;
        }
        __syncwarp();

        // O += P V  (16x64 per warp)
        #pragma unroll
        for (int ks = 0; ks < 8; ks++) {
            const int k0 = ks * 8;
            unsigned af[4];
            af[0] = __float_as_uint(St[(mrow + fr) * AP + k0 + fc]);
            af[1] = __float_as_uint(St[(mrow + fr + 8) * AP + k0 + fc]);
            af[2] = __float_as_uint(St[(mrow + fr) * AP + k0 + fc + 4]);
            af[3] = __float_as_uint(St[(mrow + fr + 8) * AP + k0 + fc + 4]);
            #pragma unroll
            for (int ntl = 0; ntl < 8; ntl++) {
                unsigned bf[2];
                bf[0] = __float_as_uint(Vs[(k0 + fc) * AP + ntl * 8 + fr]);
                bf[1] = __float_as_uint(Vs[(k0 + fc + 4) * AP + ntl * 8 + fr]);
                mma_tf32(o[ntl], af, bf);
            }
        }
        __syncthreads();
    }

    float li0 = 1.f / l0, li1 = 1.f / l1;
    #pragma unroll
    for (int ntl = 0; ntl < 8; ntl++) {
        int col = h * 64 + ntl * 8 + 2 * fc;
        long row0 = qt * 64 + mrow + fr;
        *(float2*)&out[row0 * HSIZE + col] =
            make_float2(o[ntl][0] * li0, o[ntl][1] * li0);
        *(float2*)&out[(row0 + 8) * HSIZE + col] =
            make_float2(o[ntl][2] * li1, o[ntl][3] * li1);
    }
}

// ---------------- LaCT helpers ----------------
// xn[s, h*256+d] -> c[ch, cc, d]   (ch = n*4+h)
__global__ void reshape_kernel(const float* __restrict__ xn, float* __restrict__ c) {
    int idx = blockIdx.x * 256 + threadIdx.x;
    int d  = idx & 255;
    int cc = (idx >> 8) & 1023;
    int ch = idx >> 18;
    int n = ch >> 2, h = ch & 3;
    c[idx] = xn[(long)(n * CHUNK + cc) * HSIZE + h * DIN + d];
}

// out[s, h*256+d] += oq[ch, cc, d]
__global__ void scatter_kernel(const float* __restrict__ oq, float* __restrict__ out) {
    int idx = blockIdx.x * 256 + threadIdx.x;
    int d  = idx & 255;
    int cc = (idx >> 8) & 1023;
    int ch = idx >> 18;
    int n = ch >> 2, h = ch & 3;
    long o = (long)(n * CHUNK + cc) * HSIZE + h * DIN + d;
    out[o] += oq[idx];
}

// inputs: s0=gate, s1=g, s2=u (= kv@w1)
// outputs: s3=hidden, s0=P=u*g*silu'(gate), s1=Q2=u*h
__global__ void ew1_kernel(float* __restrict__ s0, float* __restrict__ s1,
                           const float* __restrict__ s2, float* __restrict__ s3) {
    int i = blockIdx.x * 256 + threadIdx.x;
    float gate = s0[i], g = s1[i], u = s2[i];
    float sg = 1.f / (1.f + __expf(-gate));
    float hh = gate * sg;
    s3[i] = hh * g;
    s0[i] = u * g * sg * (1.f + gate * (1.f - sg));
    s1[i] = u * hh;
}

// s2 = silu(s0) * s1
__global__ void ew2_kernel(const float* __restrict__ s0, const float* __restrict__ s1,
                           float* __restrict__ s2) {
    int i = blockIdx.x * 256 + threadIdx.x;
    float gq = s0[i], gq2 = s1[i];
    float sg = 1.f / (1.f + __expf(-gq));
    s2[i] = gq * sg * gq2;
}

// ---------------- host launcher ----------------
static void run_gemm(int M, int N, int K,
                     const float* A, int lda, int tA, long sA, int mA,
                     const float* B, int ldb, int tB, long sB, int mB,
                     float* C, int ldc, long sC, int mC,
                     const float* bias,
                     const float* base, int ldbase, long sBase, int mBase,
                     int batch) {
    GemmParams p;
    p.A = A; p.lda = lda; p.transA = tA; p.strideA = sA; p.modA = mA > 0 ? mA : 1;
    p.B = B; p.ldb = ldb; p.transB = tB; p.strideB = sB; p.modB = mB > 0 ? mB : 1;
    p.C = C; p.ldc = ldc; p.strideC = sC; p.modC = mC > 0 ? mC : 1;
    p.bias = bias;
    p.base = base; p.ldbase = ldbase; p.strideBase = sBase; p.modBase = mBase > 0 ? mBase : 1;
    p.M = M; p.N = N; p.K = K;
    dim3 grid(N / 128, M / 128, batch);
    tgemm_kernel<<<grid, 256>>>(p);
}

extern "C" void kernel_launch(void* const* d_in, const int* in_sizes, int n_in,
                              void* d_out, int out_size) {
    const float* x     = (const float*)d_in[0];
    const float* ln_w  = (const float*)d_in[1];
    const float* ln_b  = (const float*)d_in[2];
    const float* in_w  = (const float*)d_in[3];
    const float* in_b  = (const float*)d_in[4];
    const float* ou_w  = (const float*)d_in[5];
    const float* ou_b  = (const float*)d_in[6];
    const float* w0    = (const float*)d_in[7];
    const float* w1    = (const float*)d_in[8];
    const float* w2    = (const float*)d_in[9];
    float* out = (float*)d_out;

    float* scr = nullptr;
    cudaGetSymbolAddress((void**)&scr, g_scratch);
    float* xn   = scr + OFF_XN;
    float* qkvb = scr + OFF_QKV;
    float* attn = scr + OFF_ATTN;
    float* cbuf = scr + OFF_C;
    float* s0   = scr + OFF_S0;
    float* s1   = scr + OFF_S1;
    float* s2   = scr + OFF_S2;
    float* s3   = scr + OFF_S3;
    float* w0n  = scr + OFF_W0N;
    float* w1n  = scr + OFF_W1N;
    float* w2n  = scr + OFF_W2N;

    // 1. LayerNorm
    ln_kernel<<<S_LEN, 256>>>(x, ln_w, ln_b, xn);

    // 2. qkv = xn @ in_proj_w^T + b   [4096,3072]
    run_gemm(4096, 3072, 1024,
             xn, 1024, 0, 0, 1,
             in_w, 1024, 1, 0, 1,
             qkvb, 3072, 0, 1,
             in_b, nullptr, 0, 0, 1, 1);

    // 3. contiguous kv per chunk-head
    reshape_kernel<<<16384, 256>>>(xn, cbuf);

    // 4. tensor-core flash attention
    cudaFuncSetAttribute(attn_tc_kernel, cudaFuncAttributeMaxDynamicSharedMemorySize,
                         ATT_SMEM_FLOATS * 4);
    attn_tc_kernel<<<dim3(64, 16), 128, ATT_SMEM_FLOATS * 4>>>(qkvb, attn);

    // 5. attn_out = attn @ out_proj_w^T + b  -> d_out
    run_gemm(4096, 1024, 1024,
             attn, 1024, 0, 0, 1,
             ou_w, 1024, 1, 0, 1,
             out, 1024, 0, 1,
             ou_b, nullptr, 0, 0, 1, 1);

    // 6. gate = kv @ w0^T ; g = kv @ w2^T ; u = kv @ w1  (batched over 16 chunk-heads)
    run_gemm(1024, 256, 256,
             cbuf, 256, 0, CHD_STRIDE, 16,
             w0, 256, 1, W_STRIDE, 4,
             s0, 256, CHD_STRIDE, 16,
             nullptr, nullptr, 0, 0, 1, 16);
    run_gemm(1024, 256, 256,
             cbuf, 256, 0, CHD_STRIDE, 16,
             w2, 256, 1, W_STRIDE, 4,
             s1, 256, CHD_STRIDE, 16,
             nullptr, nullptr, 0, 0, 1, 16);
    run_gemm(1024, 256, 256,
             cbuf, 256, 0, CHD_STRIDE, 16,
             w1, 256, 0, W_STRIDE, 4,
             s2, 256, CHD_STRIDE, 16,
             nullptr, nullptr, 0, 0, 1, 16);

    // 7. elementwise: hidden, P, Q2
    ew1_kernel<<<16384, 256>>>(s0, s1, s2, s3);

    // 8. w1n = w1 + kv^T @ hidden ; w0n = w0 + P^T @ kv ; w2n = w2 + Q2^T @ kv
    run_gemm(256, 256, 1024,
             cbuf, 256, 1, CHD_STRIDE, 16,
             s3, 256, 0, CHD_STRIDE, 16,
             w1n, 256, W_STRIDE, 16,
             nullptr, w1, 256, W_STRIDE, 4, 16);
    run_gemm(256, 256, 1024,
             s0, 256, 1, CHD_STRIDE, 16,
             cbuf, 256, 0, CHD_STRIDE, 16,
             w0n, 256, W_STRIDE, 16,
             nullptr, w0, 256, W_STRIDE, 4, 16);
    run_gemm(256, 256, 1024,
             s1, 256, 1, CHD_STRIDE, 16,
             cbuf, 256, 0, CHD_STRIDE, 16,
             w2n, 256, W_STRIDE, 16,
             nullptr, w2, 256, W_STRIDE, 4, 16);

    // 9. gq = kv @ w0n^T ; gq2 = kv @ w2n^T
    run_gemm(1024, 256, 256,
             cbuf, 256, 0, CHD_STRIDE, 16,
             w0n, 256, 1, W_STRIDE, 16,
             s0, 256, CHD_STRIDE, 16,
             nullptr, nullptr, 0, 0, 1, 16);
    run_gemm(1024, 256, 256,
             cbuf, 256, 0, CHD_STRIDE, 16,
             w2n, 256, 1, W_STRIDE, 16,
             s1, 256, CHD_STRIDE, 16,
             nullptr, nullptr, 0, 0, 1, 16);

    // 10. X = silu(gq) * gq2
    ew2_kernel<<<16384, 256>>>(s0, s1, s2);

    // 11. oq = X @ w1n^T
    run_gemm(1024, 256, 256,
             s2, 256, 0, CHD_STRIDE, 16,
             w1n, 256, 1, W_STRIDE, 16,
             s3, 256, CHD_STRIDE, 16,
             nullptr, nullptr, 0, 0, 1, 16);

    // 12. d_out += scattered oq
    scatter_kernel<<<16384, 256>>>(s3, out);
}

// round 5
// speedup vs baseline: 2.3073x; 1.0982x over previous
#include <cuda_runtime.h>
#include <math.h>

// ---------------- problem constants ----------------
#define S_LEN 4096
#define HSIZE 1024
#define NHA   16
#define HD    64
#define NHL   4
#define DIN   256
#define CHUNK 1024
#define NC    4
#define NCH   16   // NC * NHL

// scratch offsets (in floats)
#define OFF_XN    0L
#define OFF_QKV   4194304L
#define OFF_ATTN  16777216L
#define OFF_C     20971520L
#define OFF_S0    25165824L
#define OFF_S1    29360128L
#define OFF_S2    33554432L
#define OFF_S3    37748736L
#define OFF_W0N   41943040L
#define OFF_W1N   42991616L
#define OFF_W2N   44040192L
#define SCRATCH_TOTAL 45088768L

#define CHD_STRIDE 262144L   // 1024*256 per chunk-head activation
#define W_STRIDE   65536L    // 256*256 per head weight

__device__ float g_scratch[SCRATCH_TOTAL];

// ---------------- tf32 helpers ----------------
__device__ __forceinline__ float tf32r(float x) {
    unsigned r;
    asm("cvt.rna.tf32.f32 %0, %1;" : "=r"(r) : "f"(x));
    return __uint_as_float(r);
}

__device__ __forceinline__ void mma_tf32(float* c, const unsigned* a, const unsigned* b) {
    asm volatile(
        "mma.sync.aligned.m16n8k8.row.col.f32.tf32.tf32.f32 "
        "{%0,%1,%2,%3}, {%4,%5,%6,%7}, {%8,%9}, {%0,%1,%2,%3};"
        : "+f"(c[0]), "+f"(c[1]), "+f"(c[2]), "+f"(c[3])
        : "r"(a[0]), "r"(a[1]), "r"(a[2]), "r"(a[3]), "r"(b[0]), "r"(b[1]));
}

// ---------------- LayerNorm (fused chunk-head reshape) ----------------
__global__ void ln_kernel(const float* __restrict__ x,
                          const float* __restrict__ w,
                          const float* __restrict__ b,
                          float* __restrict__ out,
                          float* __restrict__ cbuf) {
    int row = blockIdx.x;
    const float* xr = x + (long)row * HSIZE;
    float s = 0.f, ss = 0.f;
    for (int i = threadIdx.x; i < HSIZE; i += blockDim.x) {
        float v = xr[i]; s += v; ss += v * v;
    }
    __shared__ float red[64];
    for (int o = 16; o > 0; o >>= 1) {
        s  += __shfl_down_sync(0xffffffffu, s,  o);
        ss += __shfl_down_sync(0xffffffffu, ss, o);
    }
    int wid = threadIdx.x >> 5, lid = threadIdx.x & 31;
    if (lid == 0) { red[wid] = s; red[wid + 32] = ss; }
    __syncthreads();
    if (threadIdx.x == 0) {
        float ts = 0.f, tss = 0.f;
        int nw = blockDim.x >> 5;
        for (int i = 0; i < nw; i++) { ts += red[i]; tss += red[i + 32]; }
        float mean = ts / HSIZE;
        red[0] = mean;
        red[1] = tss / HSIZE - mean * mean;
    }
    __syncthreads();
    float mean = red[0];
    float inv = rsqrtf(red[1] + 1e-5f);
    float* orow = out + (long)row * HSIZE;
    int n = row >> 10, cc = row & 1023;
    for (int i = threadIdx.x; i < HSIZE; i += blockDim.x) {
        float v = (xr[i] - mean) * inv * w[i] + b[i];
        orow[i] = v;
        int h = i >> 8, d = i & 255;
        cbuf[(long)(n * 4 + h) * CHD_STRIDE + (long)cc * 256 + d] = v;
    }
}

// ---------------- generic batched TF32 tensor-core GEMM ----------------
struct GemmParams {
    const float* A; int lda; int transA; long strideA; int modA;
    const float* B; int ldb; int transB; long strideB; int modB;
    float* C; int ldc; long strideC; int modC;
    const float* bias;
    const float* base; int ldbase; long strideBase; int modBase;
    int M, N, K;
};

#define GP 136   // smem pitch (floats)

__global__ __launch_bounds__(256) void tgemm_kernel(GemmParams p) {
    __shared__ float As[2][16 * GP];
    __shared__ float Bs[2][16 * GP];

    const int z = blockIdx.z;
    const float* A = p.A + (long)(z % p.modA) * p.strideA;
    const float* B = p.B + (long)(z % p.modB) * p.strideB;
    float* C = p.C + (long)(z % p.modC) * p.strideC;
    const float* base = p.base ? p.base + (long)(z % p.modBase) * p.strideBase : nullptr;

    const int m0 = blockIdx.y * 128;
    const int n0 = blockIdx.x * 128;
    const int tid = threadIdx.x;
    const int lane = tid & 31, w = tid >> 5;
    const int wm = (w >> 2) * 64;
    const int wn = (w & 3) * 32;
    const int fr = lane >> 2, fc = lane & 3;

    float acc[4][4][4];
    #pragma unroll
    for (int i = 0; i < 4; i++)
        #pragma unroll
        for (int j = 0; j < 4; j++)
            #pragma unroll
            for (int q = 0; q < 4; q++) acc[i][j][q] = 0.f;

    float4 ra0, ra1, rb0, rb1;

    auto loadA = [&](int k0) {
        if (!p.transA) {
            int m = tid >> 1, kq = (tid & 1) * 8;
            const float* src = A + (long)(m0 + m) * p.lda + k0 + kq;
            ra0 = *(const float4*)src;
            ra1 = *(const float4*)(src + 4);
        } else {
            int k1 = tid >> 5, m4 = (tid & 31) * 4;
            ra0 = *(const float4*)(A + (long)(k0 + k1) * p.lda + m0 + m4);
            int id = tid + 256;
            int k2 = id >> 5, m42 = (id & 31) * 4;
            ra1 = *(const float4*)(A + (long)(k0 + k2) * p.lda + m0 + m42);
        }
    };
    auto storeA = [&](int buf) {
        float* s = As[buf];
        if (!p.transA) {
            int m = tid >> 1, kq = (tid & 1) * 8;
            s[(kq + 0) * GP + m] = tf32r(ra0.x);
            s[(kq + 1) * GP + m] = tf32r(ra0.y);
            s[(kq + 2) * GP + m] = tf32r(ra0.z);
            s[(kq + 3) * GP + m] = tf32r(ra0.w);
            s[(kq + 4) * GP + m] = tf32r(ra1.x);
            s[(kq + 5) * GP + m] = tf32r(ra1.y);
            s[(kq + 6) * GP + m] = tf32r(ra1.z);
            s[(kq + 7) * GP + m] = tf32r(ra1.w);
        } else {
            int k1 = tid >> 5, m4 = (tid & 31) * 4;
            s[k1 * GP + m4 + 0] = tf32r(ra0.x);
            s[k1 * GP + m4 + 1] = tf32r(ra0.y);
            s[k1 * GP + m4 + 2] = tf32r(ra0.z);
            s[k1 * GP + m4 + 3] = tf32r(ra0.w);
            int id = tid + 256;
            int k2 = id >> 5, m42 = (id & 31) * 4;
            s[k2 * GP + m42 + 0] = tf32r(ra1.x);
            s[k2 * GP + m42 + 1] = tf32r(ra1.y);
            s[k2 * GP + m42 + 2] = tf32r(ra1.z);
            s[k2 * GP + m42 + 3] = tf32r(ra1.w);
        }
    };
    auto loadB = [&](int k0) {
        if (p.transB) {
            int n = tid >> 1, kq = (tid & 1) * 8;
            const float* src = B + (long)(n0 + n) * p.ldb + k0 + kq;
            rb0 = *(const float4*)src;
            rb1 = *(const float4*)(src + 4);
        } else {
            int k1 = tid >> 5, n4 = (tid & 31) * 4;
            rb0 = *(const float4*)(B + (long)(k0 + k1) * p.ldb + n0 + n4);
            int id = tid + 256;
            int k2 = id >> 5, n42 = (id & 31) * 4;
            rb1 = *(const float4*)(B + (long)(k0 + k2) * p.ldb + n0 + n42);
        }
    };
    auto storeB = [&](int buf) {
        float* s = Bs[buf];
        if (p.transB) {
            int n = tid >> 1, kq = (tid & 1) * 8;
            s[(kq + 0) * GP + n] = tf32r(rb0.x);
            s[(kq + 1) * GP + n] = tf32r(rb0.y);
            s[(kq + 2) * GP + n] = tf32r(rb0.z);
            s[(kq + 3) * GP + n] = tf32r(rb0.w);
            s[(kq + 4) * GP + n] = tf32r(rb1.x);
            s[(kq + 5) * GP + n] = tf32r(rb1.y);
            s[(kq + 6) * GP + n] = tf32r(rb1.z);
            s[(kq + 7) * GP + n] = tf32r(rb1.w);
        } else {
            int k1 = tid >> 5, n4 = (tid & 31) * 4;
            s[k1 * GP + n4 + 0] = tf32r(rb0.x);
            s[k1 * GP + n4 + 1] = tf32r(rb0.y);
            s[k1 * GP + n4 + 2] = tf32r(rb0.z);
            s[k1 * GP + n4 + 3] = tf32r(rb0.w);
            int id = tid + 256;
            int k2 = id >> 5, n42 = (id & 31) * 4;
            s[k2 * GP + n42 + 0] = tf32r(rb1.x);
            s[k2 * GP + n42 + 1] = tf32r(rb1.y);
            s[k2 * GP + n42 + 2] = tf32r(rb1.z);
            s[k2 * GP + n42 + 3] = tf32r(rb1.w);
        }
    };

    const int nt = p.K >> 4;
    loadA(0); loadB(0);
    storeA(0); storeB(0);
    __syncthreads();

    for (int t = 0; t < nt; t++) {
        const int cur = t & 1;
        if (t + 1 < nt) { loadA((t + 1) << 4); loadB((t + 1) << 4); }

        #pragma unroll
        for (int ks = 0; ks < 2; ks++) {
            const int k0 = ks * 8;
            unsigned af[4][4], bf[4][2];
            #pragma unroll
            for (int mt = 0; mt < 4; mt++) {
                int m = wm + mt * 16 + fr;
                af[mt][0] = __float_as_uint(As[cur][(k0 + fc) * GP + m]);
                af[mt][1] = __float_as_uint(As[cur][(k0 + fc) * GP + m + 8]);
                af[mt][2] = __float_as_uint(As[cur][(k0 + fc + 4) * GP + m]);
                af[mt][3] = __float_as_uint(As[cur][(k0 + fc + 4) * GP + m + 8]);
            }
            #pragma unroll
            for (int ntl = 0; ntl < 4; ntl++) {
                int n = wn + ntl * 8 + fr;
                bf[ntl][0] = __float_as_uint(Bs[cur][(k0 + fc) * GP + n]);
                bf[ntl][1] = __float_as_uint(Bs[cur][(k0 + fc + 4) * GP + n]);
            }
            #pragma unroll
            for (int mt = 0; mt < 4; mt++)
                #pragma unroll
                for (int ntl = 0; ntl < 4; ntl++)
                    mma_tf32(acc[mt][ntl], af[mt], bf[ntl]);
        }

        if (t + 1 < nt) { storeA(cur ^ 1); storeB(cur ^ 1); }
        __syncthreads();
    }

    #pragma unroll
    for (int mt = 0; mt < 4; mt++) {
        int row0 = m0 + wm + mt * 16 + fr;
        #pragma unroll
        for (int ntl = 0; ntl < 4; ntl++) {
            int col = n0 + wn + ntl * 8 + 2 * fc;
            float v0 = acc[mt][ntl][0], v1 = acc[mt][ntl][1];
            float v2 = acc[mt][ntl][2], v3 = acc[mt][ntl][3];
            if (p.bias) {
                float b0 = p.bias[col], b1 = p.bias[col + 1];
                v0 += b0; v1 += b1; v2 += b0; v3 += b1;
            }
            if (base) {
                v0 += base[(long)row0 * p.ldbase + col];
                v1 += base[(long)row0 * p.ldbase + col + 1];
                v2 += base[(long)(row0 + 8) * p.ldbase + col];
                v3 += base[(long)(row0 + 8) * p.ldbase + col + 1];
            }
            *(float2*)&C[(long)row0 * p.ldc + col] = make_float2(v0, v1);
            *(float2*)&C[(long)(row0 + 8) * p.ldc + col] = make_float2(v2, v3);
        }
    }
}

// ---------------- tensor-core flash attention (128-row Q tile, 8 warps) ----
// grid (32 q-tiles, 16 heads), 256 threads. Warp w owns rows w*16..w*16+15.
// K/V stored row-major in smem; register-prefetch double buffering of K/V.
#define AP 68
#define BQ 128
#define ATT_SMEM_FLOATS ((BQ + 64 + 64 + BQ) * AP)
__global__ __launch_bounds__(256) void attn_tc_kernel(const float* __restrict__ qkv,
                                                      float* __restrict__ out) {
    extern __shared__ float sm[];
    float* Qs = sm;                    // [m][d]     pitch AP
    float* Ks = sm + BQ * AP;          // [key][d]
    float* Vs = sm + (BQ + 64) * AP;   // [key][d]
    float* St = sm + (BQ + 128) * AP;  // [row][key]

    const int h = blockIdx.y, qt = blockIdx.x;
    const int tid = threadIdx.x, lane = tid & 31, w = tid >> 5;
    const int fr = lane >> 2, fc = lane & 3;
    const int mrow = w * 16;

    // load Q tile (scaled, tf32): 128x64
    for (int i = tid; i < BQ * 16; i += 256) {
        int row = i >> 4, dq = (i & 15) * 4;
        float4 v = *(const float4*)(qkv + (long)(qt * BQ + row) * 3072 + h * 64 + dq);
        *(float4*)&Qs[row * AP + dq] = make_float4(
            tf32r(v.x * 0.125f), tf32r(v.y * 0.125f),
            tf32r(v.z * 0.125f), tf32r(v.w * 0.125f));
    }

    float o[8][4];
    #pragma unroll
    for (int i = 0; i < 8; i++)
        #pragma unroll
        for (int j = 0; j < 4; j++) o[i][j] = 0.f;
    float m0 = -1e30f, m1 = -1e30f, l0 = 0.f, l1 = 0.f;

    float4 pk[4], pv[4];
    auto loadKV = [&](int kt) {
        #pragma unroll
        for (int j = 0; j < 4; j++) {
            int u = tid + j * 256;
            int row = u >> 4, dq = (u & 15) * 4;
            long bidx = (long)(kt * 64 + row) * 3072 + h * 64 + dq;
            pk[j] = *(const float4*)(qkv + bidx + 1024);
            pv[j] = *(const float4*)(qkv + bidx + 2048);
        }
    };
    auto storeKV = [&]() {
        #pragma unroll
        for (int j = 0; j < 4; j++) {
            int u = tid + j * 256;
            int row = u >> 4, dq = (u & 15) * 4;
            *(float4*)&Ks[row * AP + dq] = make_float4(
                tf32r(pk[j].x), tf32r(pk[j].y), tf32r(pk[j].z), tf32r(pk[j].w));
            *(float4*)&Vs[row * AP + dq] = make_float4(
                tf32r(pv[j].x), tf32r(pv[j].y), tf32r(pv[j].z), tf32r(pv[j].w));
        }
    };

    loadKV(0);
    storeKV();
    __syncthreads();

    for (int kt = 0; kt < 64; kt++) {
        if (kt + 1 < 64) loadKV(kt + 1);

        // S = Q K^T  (16x64 per warp)
        float s[8][4];
        #pragma unroll
        for (int i = 0; i < 8; i++)
            #pragma unroll
            for (int j = 0; j < 4; j++) s[i][j] = 0.f;
        #pragma unroll
        for (int ks = 0; ks < 8; ks++) {
            const int k0 = ks * 8;
            unsigned af[4];
            af[0] = __float_as_uint(Qs[(mrow + fr) * AP + k0 + fc]);
            af[1] = __float_as_uint(Qs[(mrow + fr + 8) * AP + k0 + fc]);
            af[2] = __float_as_uint(Qs[(mrow + fr) * AP + k0 + fc + 4]);
            af[3] = __float_as_uint(Qs[(mrow + fr + 8) * AP + k0 + fc + 4]);
            #pragma unroll
            for (int ntl = 0; ntl < 8; ntl++) {
                unsigned bf[2];
                bf[0] = __float_as_uint(Ks[(ntl * 8 + fr) * AP + k0 + fc]);
                bf[1] = __float_as_uint(Ks[(ntl * 8 + fr) * AP + k0 + fc + 4]);
                mma_tf32(s[ntl], af, bf);
            }
        }

        // online softmax
        float mx0 = m0, mx1 = m1;
        #pragma unroll
        for (int ntl = 0; ntl < 8; ntl++) {
            mx0 = fmaxf(mx0, fmaxf(s[ntl][0], s[ntl][1]));
            mx1 = fmaxf(mx1, fmaxf(s[ntl][2], s[ntl][3]));
        }
        mx0 = fmaxf(mx0, __shfl_xor_sync(0xffffffffu, mx0, 1));
        mx0 = fmaxf(mx0, __shfl_xor_sync(0xffffffffu, mx0, 2));
        mx1 = fmaxf(mx1, __shfl_xor_sync(0xffffffffu, mx1, 1));
        mx1 = fmaxf(mx1, __shfl_xor_sync(0xffffffffu, mx1, 2));

        float sum0 = 0.f, sum1 = 0.f;
        #pragma unroll
        for (int ntl = 0; ntl < 8; ntl++) {
            int col = ntl * 8 + 2 * fc;
            float p0 = __expf(s[ntl][0] - mx0);
            float p1 = __expf(s[ntl][1] - mx0);
            float p2 = __expf(s[ntl][2] - mx1);
            float p3 = __expf(s[ntl][3] - mx1);
            sum0 += p0 + p1;
            sum1 += p2 + p3;
            *(float2*)&St[(mrow + fr) * AP + col] = make_float2(tf32r(p0), tf32r(p1));
            *(float2*)&St[(mrow + fr + 8) * AP + col] = make_float2(tf32r(p2), tf32r(p3));
        }
        sum0 += __shfl_xor_sync(0xffffffffu, sum0, 1);
        sum0 += __shfl_xor_sync(0xffffffffu, sum0, 2);
        sum1 += __shfl_xor_sync(0xffffffffu, sum1, 1);
        sum1 += __shfl_xor_sync(0xffffffffu, sum1, 2);

        float al0 = __expf(m0 - mx0);
        float al1 = __expf(m1 - mx1);
        l0 = l0 * al0 + sum0;
        l1 = l1 * al1 + sum1;
        m0 = mx0; m1 = mx1;
        #pragma unroll
        for (int ntl = 0; ntl < 8; ntl++) {
            o[ntl][0] *= al0; o[ntl][1] *= al0;
            o[ntl][2] *= al1; o[ntl][3] *= al1;
        }
        __syncwarp();

        // O += P V
        #pragma unroll
        for (int ks = 0; ks < 8; ks++) {
            const int k0 = ks * 8;
            unsigned af[4];
            af[0] = __float_as_uint(St[(mrow + fr) * AP + k0 + fc]);
            af[1] = __float_as_uint(St[(mrow + fr + 8) * AP + k0 + fc]);
            af[2] = __float_as_uint(St[(mrow + fr) * AP + k0 + fc + 4]);
            af[3] = __float_as_uint(St[(mrow + fr + 8) * AP + k0 + fc + 4]);
            #pragma unroll
            for (int ntl = 0; ntl < 8; ntl++) {
                unsigned bf[2];
                bf[0] = __float_as_uint(Vs[(k0 + fc) * AP + ntl * 8 + fr]);
                bf[1] = __float_as_uint(Vs[(k0 + fc + 4) * AP + ntl * 8 + fr]);
                mma_tf32(o[ntl], af, bf);
            }
        }
        __syncthreads();          // everyone done reading Ks/Vs
        if (kt + 1 < 64) {
            storeKV();
            __syncthreads();
        }
    }

    float li0 = 1.f / l0, li1 = 1.f / l1;
    #pragma unroll
    for (int ntl = 0; ntl < 8; ntl++) {
        int col = h * 64 + ntl * 8 + 2 * fc;
        long row0 = qt * BQ + mrow + fr;
        *(float2*)&out[row0 * HSIZE + col] =
            make_float2(o[ntl][0] * li0, o[ntl][1] * li0);
        *(float2*)&out[(row0 + 8) * HSIZE + col] =
            make_float2(o[ntl][2] * li1, o[ntl][3] * li1);
    }
}

// ---------------- LaCT elementwise ----------------
// inputs: s0=gate, s1=g, s2=u (= kv@w1)
// outputs: s3=hidden, s0=P=u*g*silu'(gate), s1=Q2=u*h
__global__ void ew1_kernel(float* __restrict__ s0, float* __restrict__ s1,
                           const float* __restrict__ s2, float* __restrict__ s3) {
    int i = blockIdx.x * 256 + threadIdx.x;
    float gate = s0[i], g = s1[i], u = s2[i];
    float sg = 1.f / (1.f + __expf(-gate));
    float hh = gate * sg;
    s3[i] = hh * g;
    s0[i] = u * g * sg * (1.f + gate * (1.f - sg));
    s1[i] = u * hh;
}

// s2 = silu(s0) * s1
__global__ void ew2_kernel(const float* __restrict__ s0, const float* __restrict__ s1,
                           float* __restrict__ s2) {
    int i = blockIdx.x * 256 + threadIdx.x;
    float gq = s0[i], gq2 = s1[i];
    float sg = 1.f / (1.f + __expf(-gq));
    s2[i] = gq * sg * gq2;
}

// ---------------- host launcher ----------------
static void run_gemm(int M, int N, int K,
                     const float* A, int lda, int tA, long sA, int mA,
                     const float* B, int ldb, int tB, long sB, int mB,
                     float* C, int ldc, long sC, int mC,
                     const float* bias,
                     const float* base, int ldbase, long sBase, int mBase,
                     int batch) {
    GemmParams p;
    p.A = A; p.lda = lda; p.transA = tA; p.strideA = sA; p.modA = mA > 0 ? mA : 1;
    p.B = B; p.ldb = ldb; p.transB = tB; p.strideB = sB; p.modB = mB > 0 ? mB : 1;
    p.C = C; p.ldc = ldc; p.strideC = sC; p.modC = mC > 0 ? mC : 1;
    p.bias = bias;
    p.base = base; p.ldbase = ldbase; p.strideBase = sBase; p.modBase = mBase > 0 ? mBase : 1;
    p.M = M; p.N = N; p.K = K;
    dim3 grid(N / 128, M / 128, batch);
    tgemm_kernel<<<grid, 256>>>(p);
}

extern "C" void kernel_launch(void* const* d_in, const int* in_sizes, int n_in,
                              void* d_out, int out_size) {
    const float* x     = (const float*)d_in[0];
    const float* ln_w  = (const float*)d_in[1];
    const float* ln_b  = (const float*)d_in[2];
    const float* in_w  = (const float*)d_in[3];
    const float* in_b  = (const float*)d_in[4];
    const float* ou_w  = (const float*)d_in[5];
    const float* ou_b  = (const float*)d_in[6];
    const float* w0    = (const float*)d_in[7];
    const float* w1    = (const float*)d_in[8];
    const float* w2    = (const float*)d_in[9];
    float* out = (float*)d_out;

    float* scr = nullptr;
    cudaGetSymbolAddress((void**)&scr, g_scratch);
    float* xn   = scr + OFF_XN;
    float* qkvb = scr + OFF_QKV;
    float* cbuf = scr + OFF_C;
    float* s0   = scr + OFF_S0;
    float* s1   = scr + OFF_S1;
    float* s2   = scr + OFF_S2;
    float* s3   = scr + OFF_S3;
    float* w0n  = scr + OFF_W0N;
    float* w1n  = scr + OFF_W1N;
    float* w2n  = scr + OFF_W2N;
    float* attn = scr + OFF_ATTN;

    // 1. LayerNorm (+ fused reshape into cbuf)
    ln_kernel<<<S_LEN, 256>>>(x, ln_w, ln_b, xn, cbuf);

    // 2. qkv = xn @ in_proj_w^T + b   [4096,3072]
    run_gemm(4096, 3072, 1024,
             xn, 1024, 0, 0, 1,
             in_w, 1024, 1, 0, 1,
             qkvb, 3072, 0, 1,
             in_b, nullptr, 0, 0, 1, 1);

    // 3. tensor-core flash attention
    cudaFuncSetAttribute(attn_tc_kernel, cudaFuncAttributeMaxDynamicSharedMemorySize,
                         ATT_SMEM_FLOATS * 4);
    attn_tc_kernel<<<dim3(32, 16), 256, ATT_SMEM_FLOATS * 4>>>(qkvb, attn);

    // 4. attn_out = attn @ out_proj_w^T + b  -> d_out
    run_gemm(4096, 1024, 1024,
             attn, 1024, 0, 0, 1,
             ou_w, 1024, 1, 0, 1,
             out, 1024, 0, 1,
             ou_b, nullptr, 0, 0, 1, 1);

    // 5. gate = kv @ w0^T ; g = kv @ w2^T ; u = kv @ w1  (batched, 16 chunk-heads)
    run_gemm(1024, 256, 256,
             cbuf, 256, 0, CHD_STRIDE, 16,
             w0, 256, 1, W_STRIDE, 4,
             s0, 256, CHD_STRIDE, 16,
             nullptr, nullptr, 0, 0, 1, 16);
    run_gemm(1024, 256, 256,
             cbuf, 256, 0, CHD_STRIDE, 16,
             w2, 256, 1, W_STRIDE, 4,
             s1, 256, CHD_STRIDE, 16,
             nullptr, nullptr, 0, 0, 1, 16);
    run_gemm(1024, 256, 256,
             cbuf, 256, 0, CHD_STRIDE, 16,
             w1, 256, 0, W_STRIDE, 4,
             s2, 256, CHD_STRIDE, 16,
             nullptr, nullptr, 0, 0, 1, 16);

    // 6. elementwise: hidden, P, Q2
    ew1_kernel<<<16384, 256>>>(s0, s1, s2, s3);

    // 7. w1n = w1 + kv^T @ hidden ; w0n = w0 + P^T @ kv ; w2n = w2 + Q2^T @ kv
    run_gemm(256, 256, 1024,
             cbuf, 256, 1, CHD_STRIDE, 16,
             s3, 256, 0, CHD_STRIDE, 16,
             w1n, 256, W_STRIDE, 16,
             nullptr, w1, 256, W_STRIDE, 4, 16);
    run_gemm(256, 256, 1024,
             s0, 256, 1, CHD_STRIDE, 16,
             cbuf, 256, 0, CHD_STRIDE, 16,
             w0n, 256, W_STRIDE, 16,
             nullptr, w0, 256, W_STRIDE, 4, 16);
    run_gemm(256, 256, 1024,
             s1, 256, 1, CHD_STRIDE, 16,
             cbuf, 256, 0, CHD_STRIDE, 16,
             w2n, 256, W_STRIDE, 16,
             nullptr, w2, 256, W_STRIDE, 4, 16);

    // 8. gq = kv @ w0n^T ; gq2 = kv @ w2n^T
    run_gemm(1024, 256, 256,
             cbuf, 256, 0, CHD_STRIDE, 16,
             w0n, 256, 1, W_STRIDE, 16,
             s0, 256, CHD_STRIDE, 16,
             nullptr, nullptr, 0, 0, 1, 16);
    run_gemm(1024, 256, 256,
             cbuf, 256, 0, CHD_STRIDE, 16,
             w2n, 256, 1, W_STRIDE, 16,
             s1, 256, CHD_STRIDE, 16,
             nullptr, nullptr, 0, 0, 1, 16);

    // 9. X = silu(gq) * gq2
    ew2_kernel<<<16384, 256>>>(s0, s1, s2);

    // 10. oq = X @ w1n^T scattered-accumulated directly into d_out
    //     (4 launches, one per lact head h; batch over the 4 chunks)
    for (int h = 0; h < 4; h++) {
        run_gemm(1024, 256, 256,
                 s2 + (long)h * CHD_STRIDE, 256, 0, 4 * CHD_STRIDE, 4,
                 w1n + (long)h * W_STRIDE, 256, 1, 4 * W_STRIDE, 4,
                 out + (long)h * 256, 1024, 1024L * 1024L, 4,
                 nullptr,
                 out + (long)h * 256, 1024, 1024L * 1024L, 4, 4);
    }
}